// round 1
// baseline (speedup 1.0000x reference)
#include <cuda_runtime.h>
#include <cuda_bf16.h>
#include <math.h>
#include <stdint.h>

#define N0c 100000
#define N1c 200000
#define NNZc 400000
#define Dc 256

// ---------------- scratch (device globals; no allocation allowed) ----------
__device__ float g_msg[(size_t)N0c * Dc];   // x_0 @ W  (102.4 MB)
__device__ int   g_count[N1c];
__device__ int   g_start[N1c];
__device__ int   g_cursor[N1c];
__device__ int   g_edge[NNZc];
__device__ int   g_bsums[128];

// ---------------- CSR build --------------------------------------------------
__global__ void k_zero_count() {
    int i = blockIdx.x * blockDim.x + threadIdx.x;
    if (i < N1c) g_count[i] = 0;
}

__global__ void k_hist(const int* __restrict__ rows) {
    int i = blockIdx.x * blockDim.x + threadIdx.x;
    if (i < NNZc) atomicAdd(&g_count[rows[i]], 1);
}

// 2048 elements per block, 98 blocks
__global__ void k_scan_a() {
    __shared__ int s[256];
    int tid  = threadIdx.x;
    int base = blockIdx.x * 2048;
    int vals[8];
    int sum = 0;
#pragma unroll
    for (int i = 0; i < 8; i++) {
        int idx = base + tid * 8 + i;
        int v = (idx < N1c) ? g_count[idx] : 0;
        vals[i] = sum;           // exclusive within thread
        sum += v;
    }
    s[tid] = sum;
    __syncthreads();
    for (int off = 1; off < 256; off <<= 1) {
        int t = (tid >= off) ? s[tid - off] : 0;
        __syncthreads();
        s[tid] += t;
        __syncthreads();
    }
    int ex = s[tid] - sum;       // exclusive prefix of thread sums
#pragma unroll
    for (int i = 0; i < 8; i++) {
        int idx = base + tid * 8 + i;
        if (idx < N1c) g_start[idx] = ex + vals[i];
    }
    if (tid == 255) g_bsums[blockIdx.x] = s[255];
}

__global__ void k_scan_b(int nblk) {
    __shared__ int s[128];
    int tid = threadIdx.x;
    int v = (tid < nblk) ? g_bsums[tid] : 0;
    s[tid] = v;
    __syncthreads();
    for (int off = 1; off < 128; off <<= 1) {
        int t = (tid >= off) ? s[tid - off] : 0;
        __syncthreads();
        s[tid] += t;
        __syncthreads();
    }
    if (tid < nblk) g_bsums[tid] = s[tid] - v;   // exclusive
}

__global__ void k_scan_c() {
    int i = blockIdx.x * blockDim.x + threadIdx.x;
    if (i < N1c) {
        int v = g_start[i] + g_bsums[i >> 11];
        g_start[i]  = v;
        g_cursor[i] = v;
    }
}

__global__ void k_scatter(const int* __restrict__ rows) {
    int e = blockIdx.x * blockDim.x + threadIdx.x;
    if (e < NNZc) {
        int p = atomicAdd(&g_cursor[rows[e]], 1);
        g_edge[p] = e;
    }
}

// ---------------- GEMM: msg = x_0 @ W  (bf16x3 split, fp32 accumulate) -------
#define BM 128
#define BN 128
#define BK 32
#define AST 40
#define BST 40

__device__ __forceinline__ void mma16816(float* c, const uint32_t* a,
                                         uint32_t b0, uint32_t b1) {
    asm volatile(
        "mma.sync.aligned.m16n8k16.row.col.f32.bf16.bf16.f32 "
        "{%0,%1,%2,%3}, {%4,%5,%6,%7}, {%8,%9}, {%0,%1,%2,%3};\n"
        : "+f"(c[0]), "+f"(c[1]), "+f"(c[2]), "+f"(c[3])
        : "r"(a[0]), "r"(a[1]), "r"(a[2]), "r"(a[3]), "r"(b0), "r"(b1));
}

__global__ __launch_bounds__(256, 2)
void k_gemm(const float* __restrict__ X, const float* __restrict__ W) {
    __shared__ __nv_bfloat16 sAh[BM * AST];
    __shared__ __nv_bfloat16 sAl[BM * AST];
    __shared__ __nv_bfloat16 sBh[BN * BST];
    __shared__ __nv_bfloat16 sBl[BN * BST];

    int tid = threadIdx.x;
    int m0 = blockIdx.x * BM;
    int n0 = blockIdx.y * BN;
    int w = tid >> 5, lane = tid & 31;
    int wm = (w >> 2) * 64;     // warp grid 2 (m) x 4 (n)
    int wn = (w & 3) * 32;
    int g = lane >> 2, t = lane & 3;

    float acc[4][4][4];
#pragma unroll
    for (int a = 0; a < 4; a++)
#pragma unroll
        for (int b = 0; b < 4; b++)
#pragma unroll
            for (int c = 0; c < 4; c++) acc[a][b][c] = 0.f;

    for (int kb = 0; kb < Dc; kb += BK) {
        // A tile: 128 x 32 fp32 -> bf16 hi/lo
#pragma unroll
        for (int i = 0; i < 4; i++) {
            int q = tid + 256 * i;
            int row = q >> 3;
            int c4  = (q & 7) << 2;
            int gm = m0 + row;
            float4 v = make_float4(0.f, 0.f, 0.f, 0.f);
            if (gm < N0c) v = *(const float4*)&X[(size_t)gm * Dc + kb + c4];
            float vv[4] = {v.x, v.y, v.z, v.w};
#pragma unroll
            for (int j = 0; j < 4; j++) {
                __nv_bfloat16 h = __float2bfloat16(vv[j]);
                __nv_bfloat16 l = __float2bfloat16(vv[j] - __bfloat162float(h));
                sAh[row * AST + c4 + j] = h;
                sAl[row * AST + c4 + j] = l;
            }
        }
        // B tile: 32 x 128 fp32 -> bf16 hi/lo, stored transposed [n][k]
#pragma unroll
        for (int i = 0; i < 4; i++) {
            int q = tid + 256 * i;
            int kr = q >> 5;
            int nq = (q & 31) << 2;
            float4 v = *(const float4*)&W[(size_t)(kb + kr) * Dc + n0 + nq];
            float vv[4] = {v.x, v.y, v.z, v.w};
#pragma unroll
            for (int j = 0; j < 4; j++) {
                __nv_bfloat16 h = __float2bfloat16(vv[j]);
                __nv_bfloat16 l = __float2bfloat16(vv[j] - __bfloat162float(h));
                sBh[(nq + j) * BST + kr] = h;
                sBl[(nq + j) * BST + kr] = l;
            }
        }
        __syncthreads();

#pragma unroll
        for (int ks = 0; ks < 2; ks++) {
            int k16 = ks * 16;
#pragma unroll
            for (int p = 0; p < 3; p++) {   // hi*hi, lo*hi, hi*lo
                const __nv_bfloat16* A = (p == 1) ? sAl : sAh;
                const __nv_bfloat16* B = (p == 2) ? sBl : sBh;
                uint32_t a[4][4];
#pragma unroll
                for (int mi = 0; mi < 4; mi++) {
                    int r = wm + mi * 16 + g;
                    a[mi][0] = *(const uint32_t*)&A[r * AST + k16 + 2 * t];
                    a[mi][1] = *(const uint32_t*)&A[(r + 8) * AST + k16 + 2 * t];
                    a[mi][2] = *(const uint32_t*)&A[r * AST + k16 + 8 + 2 * t];
                    a[mi][3] = *(const uint32_t*)&A[(r + 8) * AST + k16 + 8 + 2 * t];
                }
#pragma unroll
                for (int ni = 0; ni < 4; ni++) {
                    int n = wn + ni * 8 + g;
                    uint32_t b0 = *(const uint32_t*)&B[n * BST + k16 + 2 * t];
                    uint32_t b1 = *(const uint32_t*)&B[n * BST + k16 + 8 + 2 * t];
#pragma unroll
                    for (int mi = 0; mi < 4; mi++)
                        mma16816(acc[mi][ni], a[mi], b0, b1);
                }
            }
        }
        __syncthreads();
    }

    // store msg
#pragma unroll
    for (int mi = 0; mi < 4; mi++) {
        int r0 = m0 + wm + mi * 16 + g;
#pragma unroll
        for (int ni = 0; ni < 4; ni++) {
            int c = n0 + wn + ni * 8 + 2 * t;
            if (r0 < N0c) {
                g_msg[(size_t)r0 * Dc + c]     = acc[mi][ni][0];
                g_msg[(size_t)r0 * Dc + c + 1] = acc[mi][ni][1];
            }
            if (r0 + 8 < N0c) {
                g_msg[(size_t)(r0 + 8) * Dc + c]     = acc[mi][ni][2];
                g_msg[(size_t)(r0 + 8) * Dc + c + 1] = acc[mi][ni][3];
            }
        }
    }
}

// ---------------- pull aggregation + elu ------------------------------------
// 64 threads per output row (4 floats each), 4 rows per 256-thread block.
__global__ void k_agg(const int* __restrict__ cols,
                      const float* __restrict__ vals,
                      float* __restrict__ out) {
    int row = blockIdx.x * 4 + (threadIdx.x >> 6);
    int t = threadIdx.x & 63;
    if (row >= N1c) return;
    int s = g_start[row];
    int n = g_count[row];
    const float4* msg4 = (const float4*)g_msg;
    float4 acc = make_float4(0.f, 0.f, 0.f, 0.f);
    for (int j = 0; j < n; j++) {
        int e = g_edge[s + j];
        int c = cols[e];
        float v = vals[e];
        float4 m = msg4[(size_t)c * 64 + t];
        acc.x += v * m.x;
        acc.y += v * m.y;
        acc.z += v * m.z;
        acc.w += v * m.w;
    }
    acc.x = acc.x > 0.f ? acc.x : expm1f(acc.x);
    acc.y = acc.y > 0.f ? acc.y : expm1f(acc.y);
    acc.z = acc.z > 0.f ? acc.z : expm1f(acc.z);
    acc.w = acc.w > 0.f ? acc.w : expm1f(acc.w);
    ((float4*)out)[(size_t)row * 64 + t] = acc;
}

// ---------------- launch ------------------------------------------------------
extern "C" void kernel_launch(void* const* d_in, const int* in_sizes, int n_in,
                              void* d_out, int out_size) {
    const float* x0   = (const float*)d_in[0];
    // d_in[1] = x_1 (unused by reference)
    const int*   rows = (const int*)d_in[2];
    const int*   cols = (const int*)d_in[3];
    const float* vals = (const float*)d_in[4];
    const float* W    = (const float*)d_in[5];
    float* out = (float*)d_out;

    k_gemm<<<dim3((N0c + BM - 1) / BM, Dc / BN), 256>>>(x0, W);

    k_zero_count<<<(N1c + 255) / 256, 256>>>();
    k_hist<<<(NNZc + 255) / 256, 256>>>(rows);
    k_scan_a<<<98, 256>>>();
    k_scan_b<<<1, 128>>>(98);
    k_scan_c<<<(N1c + 255) / 256, 256>>>();
    k_scatter<<<(NNZc + 255) / 256, 256>>>(rows);

    k_agg<<<(N1c + 3) / 4, 256>>>(cols, vals, out);
}

// round 3
// speedup vs baseline: 1.5657x; 1.5657x over previous
#include <cuda_runtime.h>
#include <cuda_bf16.h>
#include <math.h>
#include <stdint.h>

#define N0c 100000
#define N1c 200000
#define NNZc 400000
#define Dc 256

// ---------------- scratch (device globals; no allocation allowed) ----------
__device__ float g_msg[(size_t)N0c * Dc];        // x_0 @ W  (102.4 MB)
__device__ __nv_bfloat16 g_XH[(size_t)N0c * Dc]; // X hi (51.2 MB)
__device__ __nv_bfloat16 g_XL[(size_t)N0c * Dc]; // X lo (51.2 MB)
__device__ __nv_bfloat16 g_WtH[Dc * Dc];         // W^T hi, [n][k]
__device__ __nv_bfloat16 g_WtL[Dc * Dc];         // W^T lo, [n][k]
__device__ int   g_count[N1c];
__device__ int   g_start[N1c];
__device__ int   g_cursor[N1c];
__device__ int   g_ecol[NNZc];
__device__ float g_eval[NNZc];
__device__ int   g_bsums[128];

// ================= helpers ===================================================
__device__ __forceinline__ uint32_t smem_u32(const void* p) {
    uint32_t a;
    asm("{ .reg .u64 t; cvta.to.shared.u64 t, %1; cvt.u32.u64 %0, t; }"
        : "=r"(a) : "l"(p));
    return a;
}
__device__ __forceinline__ void cp_async16(uint32_t dst, const void* src, int sz) {
    asm volatile("cp.async.cg.shared.global [%0], [%1], 16, %2;"
                 :: "r"(dst), "l"(__cvta_generic_to_global(src)), "r"(sz) : "memory");
}
#define CP_COMMIT() asm volatile("cp.async.commit_group;" ::: "memory")
#define CP_WAIT1()  asm volatile("cp.async.wait_group 1;" ::: "memory")
#define CP_WAIT0()  asm volatile("cp.async.wait_group 0;" ::: "memory")
#define LDSM4(r, a) \
    asm volatile("ldmatrix.sync.aligned.m8n8.x4.shared.b16 {%0,%1,%2,%3}, [%4];" \
        : "=r"((r)[0]), "=r"((r)[1]), "=r"((r)[2]), "=r"((r)[3]) : "r"(a))

__device__ __forceinline__ void mma16816(float* c, const uint32_t* a,
                                         uint32_t b0, uint32_t b1) {
    asm volatile(
        "mma.sync.aligned.m16n8k16.row.col.f32.bf16.bf16.f32 "
        "{%0,%1,%2,%3}, {%4,%5,%6,%7}, {%8,%9}, {%0,%1,%2,%3};\n"
        : "+f"(c[0]), "+f"(c[1]), "+f"(c[2]), "+f"(c[3])
        : "r"(a[0]), "r"(a[1]), "r"(a[2]), "r"(a[3]), "r"(b0), "r"(b1));
}

// ---------------- CSR build --------------------------------------------------
__global__ void k_zero_count() {
    int i = blockIdx.x * blockDim.x + threadIdx.x;
    if (i < N1c) g_count[i] = 0;
}

__global__ void k_hist(const int* __restrict__ rows) {
    int i = blockIdx.x * blockDim.x + threadIdx.x;
    if (i < NNZc) atomicAdd(&g_count[rows[i]], 1);
}

__global__ void k_scan_a() {
    __shared__ int s[256];
    int tid  = threadIdx.x;
    int base = blockIdx.x * 2048;
    int vals[8];
    int sum = 0;
#pragma unroll
    for (int i = 0; i < 8; i++) {
        int idx = base + tid * 8 + i;
        int v = (idx < N1c) ? g_count[idx] : 0;
        vals[i] = sum;
        sum += v;
    }
    s[tid] = sum;
    __syncthreads();
    for (int off = 1; off < 256; off <<= 1) {
        int t = (tid >= off) ? s[tid - off] : 0;
        __syncthreads();
        s[tid] += t;
        __syncthreads();
    }
    int ex = s[tid] - sum;
#pragma unroll
    for (int i = 0; i < 8; i++) {
        int idx = base + tid * 8 + i;
        if (idx < N1c) g_start[idx] = ex + vals[i];
    }
    if (tid == 255) g_bsums[blockIdx.x] = s[255];
}

__global__ void k_scan_b(int nblk) {
    __shared__ int s[128];
    int tid = threadIdx.x;
    int v = (tid < nblk) ? g_bsums[tid] : 0;
    s[tid] = v;
    __syncthreads();
    for (int off = 1; off < 128; off <<= 1) {
        int t = (tid >= off) ? s[tid - off] : 0;
        __syncthreads();
        s[tid] += t;
        __syncthreads();
    }
    if (tid < nblk) g_bsums[tid] = s[tid] - v;
}

__global__ void k_scan_c() {
    int i = blockIdx.x * blockDim.x + threadIdx.x;
    if (i < N1c) {
        int v = g_start[i] + g_bsums[i >> 11];
        g_start[i]  = v;
        g_cursor[i] = v;
    }
}

__global__ void k_scatter(const int* __restrict__ rows, const int* __restrict__ cols,
                          const float* __restrict__ vals) {
    int e = blockIdx.x * blockDim.x + threadIdx.x;
    if (e < NNZc) {
        int p = atomicAdd(&g_cursor[rows[e]], 1);
        g_ecol[p] = cols[e];
        g_eval[p] = vals[e];
    }
}

// ---------------- prep: W transpose + split; X split -------------------------
__global__ void k_wprep(const float* __restrict__ W) {
    int i = blockIdx.x * 256 + threadIdx.x;      // 0..65535
    int n = i >> 8, k = i & 255;
    float v = W[k * Dc + n];
    __nv_bfloat16 h = __float2bfloat16(v);
    __nv_bfloat16 l = __float2bfloat16(v - __bfloat162float(h));
    g_WtH[i] = h;
    g_WtL[i] = l;
}

__global__ void k_xprep(const float* __restrict__ X) {
    size_t i = (size_t)blockIdx.x * 256 + threadIdx.x;   // 6,400,000 float4s
    float4 v = ((const float4*)X)[i];
    float vv[4] = {v.x, v.y, v.z, v.w};
    uint32_t hp[2], lp[2];
#pragma unroll
    for (int j = 0; j < 2; j++) {
        __nv_bfloat16 h0 = __float2bfloat16(vv[2 * j]);
        __nv_bfloat16 h1 = __float2bfloat16(vv[2 * j + 1]);
        __nv_bfloat16 l0 = __float2bfloat16(vv[2 * j] - __bfloat162float(h0));
        __nv_bfloat16 l1 = __float2bfloat16(vv[2 * j + 1] - __bfloat162float(h1));
        hp[j] = (uint32_t)__bfloat16_as_ushort(h0) | ((uint32_t)__bfloat16_as_ushort(h1) << 16);
        lp[j] = (uint32_t)__bfloat16_as_ushort(l0) | ((uint32_t)__bfloat16_as_ushort(l1) << 16);
    }
    ((uint2*)g_XH)[i] = make_uint2(hp[0], hp[1]);
    ((uint2*)g_XL)[i] = make_uint2(lp[0], lp[1]);
}

// ---------------- GEMM: msg = X @ W (bf16x3, mma.sync, cp.async pipeline) ----
// CTA: 128(M) x 256(N), BK=32, 3 stages. Rows padded to 80B (40 bf16) in smem:
// ldmatrix 8-row groups hit banks (20*i)%32 -> conflict-free permutation.
#define STG_A 10240                  // one side of A tile (128 x 40 bf16)
#define STG_B 20480                  // one side of B tile (256 x 40 bf16)
#define STAGE 61440
#define OFF_AH 0
#define OFF_AL 10240
#define OFF_BH 20480
#define OFF_BL 40960
#define GEMM_SMEM (3 * STAGE)        // 184320

__device__ __forceinline__ void load_stage(uint32_t sb, int st, int m0, int tid) {
    const int kb = st * 32;
    const uint32_t base = sb + (st % 3) * STAGE;
    // A: XH/XL tiles, 1024 16B-chunks
#pragma unroll
    for (int i = 0; i < 4; i++) {
        int idx = tid + (i << 8);
        int side = idx >> 9, r = (idx >> 2) & 127, c = idx & 3;
        int gm = m0 + r;
        int ok = (gm < N0c) ? 16 : 0;
        int rr = gm < N0c ? gm : N0c - 1;
        const __nv_bfloat16* src = (side ? g_XL : g_XH) + (size_t)rr * Dc + kb + 8 * c;
        cp_async16(base + OFF_AH + side * STG_A + r * 80 + c * 16, src, ok);
    }
    // B: WtH/WtL tiles, 2048 16B-chunks
#pragma unroll
    for (int i = 0; i < 8; i++) {
        int idx = tid + (i << 8);
        int side = idx >> 10, r = (idx >> 2) & 255, c = idx & 3;
        const __nv_bfloat16* src = (side ? g_WtL : g_WtH) + r * Dc + kb + 8 * c;
        cp_async16(base + OFF_BH + side * STG_B + r * 80 + c * 16, src, 16);
    }
}

__global__ __launch_bounds__(256, 1)
void k_gemm() {
    extern __shared__ char smem[];
    const int tid = threadIdx.x;
    const int w = tid >> 5, l = tid & 31;
    const int m0 = blockIdx.x * 128;
    const uint32_t sb = smem_u32(smem);

    const int wm = (w >> 2) * 64;     // 2 (m) x 4 (n) warp grid, 64x64 tiles
    const int wn = (w & 3) * 64;
    // ldmatrix lane->address maps
    const int ra  = (l & 7) + ((l >> 3) & 1) * 8;  // A row in 16x16
    const int kca = (l >> 4) * 8;                  // A k-col
    const int rb  = (l & 7) + (l >> 4) * 8;        // B row (n) in 16x16
    const int kcb = ((l >> 3) & 1) * 8;            // B k-col

    float acc[4][8][4];
#pragma unroll
    for (int a = 0; a < 4; a++)
#pragma unroll
        for (int b = 0; b < 8; b++)
#pragma unroll
            for (int c = 0; c < 4; c++) acc[a][b][c] = 0.f;

    load_stage(sb, 0, m0, tid); CP_COMMIT();
    load_stage(sb, 1, m0, tid); CP_COMMIT();

    for (int kt = 0; kt < 8; kt++) {
        CP_WAIT1();
        __syncthreads();
        if (kt + 2 < 8) { load_stage(sb, kt + 2, m0, tid); CP_COMMIT(); }

        const uint32_t ab = sb + (kt % 3) * STAGE;
#pragma unroll
        for (int k16 = 0; k16 < 32; k16 += 16) {
            uint32_t ah[4][4], al[4][4];
#pragma unroll
            for (int mi = 0; mi < 4; mi++) {
                uint32_t arow = ab + (wm + 16 * mi + ra) * 80 + (k16 + kca) * 2;
                LDSM4(ah[mi], arow + OFF_AH);
                LDSM4(al[mi], arow + OFF_AL);
            }
#pragma unroll
            for (int ng = 0; ng < 4; ng++) {
                uint32_t brow = ab + OFF_BH + (wn + 16 * ng + rb) * 80 + (k16 + kcb) * 2;
                uint32_t bh[4], bl[4];
                LDSM4(bh, brow);
                LDSM4(bl, brow + STG_B);
#pragma unroll
                for (int mi = 0; mi < 4; mi++) {
                    mma16816(acc[mi][2 * ng],     ah[mi], bh[0], bh[1]);
                    mma16816(acc[mi][2 * ng + 1], ah[mi], bh[2], bh[3]);
                    mma16816(acc[mi][2 * ng],     al[mi], bh[0], bh[1]);
                    mma16816(acc[mi][2 * ng + 1], al[mi], bh[2], bh[3]);
                    mma16816(acc[mi][2 * ng],     ah[mi], bl[0], bl[1]);
                    mma16816(acc[mi][2 * ng + 1], ah[mi], bl[2], bl[3]);
                }
            }
        }
    }

    // epilogue: acc -> g_msg
#pragma unroll
    for (int mi = 0; mi < 4; mi++) {
#pragma unroll
        for (int h = 0; h < 2; h++) {
            int row = m0 + wm + 16 * mi + (l >> 2) + 8 * h;
            if (row < N0c) {
                float* dst = &g_msg[(size_t)row * Dc + wn + 2 * (l & 3)];
#pragma unroll
                for (int nj = 0; nj < 8; nj++) {
                    float2 f = make_float2(acc[mi][nj][2 * h], acc[mi][nj][2 * h + 1]);
                    *(float2*)(dst + 8 * nj) = f;
                }
            }
        }
    }
}

// ---------------- pull aggregation + elu ------------------------------------
__global__ void k_agg(float* __restrict__ out) {
    int row = blockIdx.x * 4 + (threadIdx.x >> 6);
    int t = threadIdx.x & 63;
    if (row >= N1c) return;
    int s = g_start[row];
    int n = g_count[row];
    const float4* msg4 = (const float4*)g_msg;
    float4 acc = make_float4(0.f, 0.f, 0.f, 0.f);
    for (int j = 0; j < n; j++) {
        int c = g_ecol[s + j];
        float v = g_eval[s + j];
        float4 m = msg4[(size_t)c * 64 + t];
        acc.x += v * m.x;
        acc.y += v * m.y;
        acc.z += v * m.z;
        acc.w += v * m.w;
    }
    acc.x = acc.x > 0.f ? acc.x : expm1f(acc.x);
    acc.y = acc.y > 0.f ? acc.y : expm1f(acc.y);
    acc.z = acc.z > 0.f ? acc.z : expm1f(acc.z);
    acc.w = acc.w > 0.f ? acc.w : expm1f(acc.w);
    ((float4*)out)[(size_t)row * 64 + t] = acc;
}

// ---------------- launch ------------------------------------------------------
extern "C" void kernel_launch(void* const* d_in, const int* in_sizes, int n_in,
                              void* d_out, int out_size) {
    const float* x0   = (const float*)d_in[0];
    const int*   rows = (const int*)d_in[2];
    const int*   cols = (const int*)d_in[3];
    const float* vals = (const float*)d_in[4];
    const float* W    = (const float*)d_in[5];
    float* out = (float*)d_out;

    static bool once = []() {
        cudaFuncSetAttribute(k_gemm, cudaFuncAttributeMaxDynamicSharedMemorySize, GEMM_SMEM);
        return true;
    }();
    (void)once;

    // order chosen so k_gemm is launch #6 (ncu -s 5 -c 1 profiles it)
    k_wprep<<<Dc, 256>>>(W);                                   // 1
    k_xprep<<<25000, 256>>>(x0);                               // 2
    k_zero_count<<<(N1c + 255) / 256, 256>>>();                // 3
    k_hist<<<(NNZc + 255) / 256, 256>>>(rows);                 // 4
    k_scan_a<<<98, 256>>>();                                   // 5
    k_gemm<<<(N0c + 127) / 128, 256, GEMM_SMEM>>>();           // 6
    k_scan_b<<<1, 128>>>(98);                                  // 7
    k_scan_c<<<(N1c + 255) / 256, 256>>>();                    // 8
    k_scatter<<<(NNZc + 255) / 256, 256>>>(rows, cols, vals);  // 9
    k_agg<<<(N1c + 3) / 4, 256>>>(out);                        // 10
}

// round 4
// speedup vs baseline: 1.6464x; 1.0516x over previous
#include <cuda_runtime.h>
#include <cuda_bf16.h>
#include <math.h>
#include <stdint.h>

#define N0c 100000
#define N1c 200000
#define NNZc 400000
#define Dc 256

// ---------------- scratch (device globals; no allocation allowed) ----------
__device__ float g_msg[(size_t)N0c * Dc];        // x_0 @ W  (102.4 MB)
__device__ __nv_bfloat16 g_XH[(size_t)N0c * Dc]; // X hi (51.2 MB)
__device__ __nv_bfloat16 g_XL[(size_t)N0c * Dc]; // X lo (51.2 MB)
__device__ __nv_bfloat16 g_WtH[Dc * Dc];         // W^T hi, [n][k]
__device__ __nv_bfloat16 g_WtL[Dc * Dc];         // W^T lo, [n][k]
__device__ int   g_count[N1c];
__device__ int   g_start[N1c];
__device__ int   g_cursor[N1c];
__device__ int   g_ecol[NNZc];
__device__ float g_eval[NNZc];
__device__ int   g_bsums[128];

// ================= helpers ===================================================
__device__ __forceinline__ uint32_t smem_u32(const void* p) {
    uint32_t a;
    asm("{ .reg .u64 t; cvta.to.shared.u64 t, %1; cvt.u32.u64 %0, t; }"
        : "=r"(a) : "l"(p));
    return a;
}
__device__ __forceinline__ void cp_async16(uint32_t dst, const void* src, int sz) {
    asm volatile("cp.async.cg.shared.global [%0], [%1], 16, %2;"
                 :: "r"(dst), "l"(__cvta_generic_to_global(src)), "r"(sz) : "memory");
}
#define CP_COMMIT() asm volatile("cp.async.commit_group;" ::: "memory")
#define CP_WAIT1()  asm volatile("cp.async.wait_group 1;" ::: "memory")
#define LDSM4(r, a) \
    asm volatile("ldmatrix.sync.aligned.m8n8.x4.shared.b16 {%0,%1,%2,%3}, [%4];" \
        : "=r"((r)[0]), "=r"((r)[1]), "=r"((r)[2]), "=r"((r)[3]) : "r"(a))

__device__ __forceinline__ void mma16816(float* c, const uint32_t* a,
                                         uint32_t b0, uint32_t b1) {
    asm volatile(
        "mma.sync.aligned.m16n8k16.row.col.f32.bf16.bf16.f32 "
        "{%0,%1,%2,%3}, {%4,%5,%6,%7}, {%8,%9}, {%0,%1,%2,%3};\n"
        : "+f"(c[0]), "+f"(c[1]), "+f"(c[2]), "+f"(c[3])
        : "r"(a[0]), "r"(a[1]), "r"(a[2]), "r"(a[3]), "r"(b0), "r"(b1));
}

// ---------------- CSR build --------------------------------------------------
__global__ void k_zero_count() {
    int i = blockIdx.x * blockDim.x + threadIdx.x;
    if (i < N1c) g_count[i] = 0;
}

__global__ void k_hist(const int* __restrict__ rows) {
    int i = blockIdx.x * blockDim.x + threadIdx.x;
    if (i < NNZc) atomicAdd(&g_count[rows[i]], 1);
}

__global__ void k_scan_a() {
    __shared__ int s[256];
    int tid  = threadIdx.x;
    int base = blockIdx.x * 2048;
    int vals[8];
    int sum = 0;
#pragma unroll
    for (int i = 0; i < 8; i++) {
        int idx = base + tid * 8 + i;
        int v = (idx < N1c) ? g_count[idx] : 0;
        vals[i] = sum;
        sum += v;
    }
    s[tid] = sum;
    __syncthreads();
    for (int off = 1; off < 256; off <<= 1) {
        int t = (tid >= off) ? s[tid - off] : 0;
        __syncthreads();
        s[tid] += t;
        __syncthreads();
    }
    int ex = s[tid] - sum;
#pragma unroll
    for (int i = 0; i < 8; i++) {
        int idx = base + tid * 8 + i;
        if (idx < N1c) g_start[idx] = ex + vals[i];
    }
    if (tid == 255) g_bsums[blockIdx.x] = s[255];
}

__global__ void k_scan_b(int nblk) {
    __shared__ int s[128];
    int tid = threadIdx.x;
    int v = (tid < nblk) ? g_bsums[tid] : 0;
    s[tid] = v;
    __syncthreads();
    for (int off = 1; off < 128; off <<= 1) {
        int t = (tid >= off) ? s[tid - off] : 0;
        __syncthreads();
        s[tid] += t;
        __syncthreads();
    }
    if (tid < nblk) g_bsums[tid] = s[tid] - v;
}

__global__ void k_scan_c() {
    int i = blockIdx.x * blockDim.x + threadIdx.x;
    if (i < N1c) {
        int v = g_start[i] + g_bsums[i >> 11];
        g_start[i]  = v;
        g_cursor[i] = v;
    }
}

__global__ void k_scatter(const int* __restrict__ rows, const int* __restrict__ cols,
                          const float* __restrict__ vals) {
    int e = blockIdx.x * blockDim.x + threadIdx.x;
    if (e < NNZc) {
        int p = atomicAdd(&g_cursor[rows[e]], 1);
        g_ecol[p] = cols[e];
        g_eval[p] = vals[e];
    }
}

// ---------------- prep: W transpose + split; X split -------------------------
__global__ void k_wprep(const float* __restrict__ W) {
    int i = blockIdx.x * 256 + threadIdx.x;      // 0..65535
    int n = i >> 8, k = i & 255;
    float v = W[k * Dc + n];
    __nv_bfloat16 h = __float2bfloat16(v);
    __nv_bfloat16 l = __float2bfloat16(v - __bfloat162float(h));
    g_WtH[i] = h;
    g_WtL[i] = l;
}

__global__ void k_xprep(const float* __restrict__ X) {
    size_t i = (size_t)blockIdx.x * 256 + threadIdx.x;   // 6,400,000 float4s
    float4 v = ((const float4*)X)[i];
    float vv[4] = {v.x, v.y, v.z, v.w};
    uint32_t hp[2], lp[2];
#pragma unroll
    for (int j = 0; j < 2; j++) {
        __nv_bfloat16 h0 = __float2bfloat16(vv[2 * j]);
        __nv_bfloat16 h1 = __float2bfloat16(vv[2 * j + 1]);
        __nv_bfloat16 l0 = __float2bfloat16(vv[2 * j] - __bfloat162float(h0));
        __nv_bfloat16 l1 = __float2bfloat16(vv[2 * j + 1] - __bfloat162float(h1));
        hp[j] = (uint32_t)__bfloat16_as_ushort(h0) | ((uint32_t)__bfloat16_as_ushort(h1) << 16);
        lp[j] = (uint32_t)__bfloat16_as_ushort(l0) | ((uint32_t)__bfloat16_as_ushort(l1) << 16);
    }
    ((uint2*)g_XH)[i] = make_uint2(hp[0], hp[1]);
    ((uint2*)g_XL)[i] = make_uint2(lp[0], lp[1]);
}

// ---------------- GEMM: msg = X @ W (bf16x3, mma.sync, cp.async pipeline) ----
// CTA: 128(M) x 256(N), BK=32, 3 stages, 512 threads (16 warps, 4x4 grid,
// warp tile 32x64). Rows padded to 80B: ldmatrix banks (20*i)%32 conflict-free.
#define STG_A 10240                  // one side of A tile (128 x 40 bf16)
#define STG_B 20480                  // one side of B tile (256 x 40 bf16)
#define STAGE 61440
#define OFF_AH 0
#define OFF_AL 10240
#define OFF_BH 20480
#define OFF_BL 40960
#define GEMM_SMEM (3 * STAGE)        // 184320

__device__ __forceinline__ void load_stage(uint32_t sb, int st, int m0, int tid) {
    const int kb = st * 32;
    const uint32_t base = sb + (st % 3) * STAGE;
    // A: XH/XL tiles, 1024 16B-chunks over 512 threads
#pragma unroll
    for (int i = 0; i < 2; i++) {
        int idx = tid + (i << 9);
        int side = idx >> 9, r = (idx >> 2) & 127, c = idx & 3;
        int gm = m0 + r;
        int ok = (gm < N0c) ? 16 : 0;
        int rr = gm < N0c ? gm : N0c - 1;
        const __nv_bfloat16* src = (side ? g_XL : g_XH) + (size_t)rr * Dc + kb + 8 * c;
        cp_async16(base + OFF_AH + side * STG_A + r * 80 + c * 16, src, ok);
    }
    // B: WtH/WtL tiles, 2048 16B-chunks
#pragma unroll
    for (int i = 0; i < 4; i++) {
        int idx = tid + (i << 9);
        int side = idx >> 10, r = (idx >> 2) & 255, c = idx & 3;
        const __nv_bfloat16* src = (side ? g_WtL : g_WtH) + r * Dc + kb + 8 * c;
        cp_async16(base + OFF_BH + side * STG_B + r * 80 + c * 16, src, 16);
    }
}

__global__ __launch_bounds__(512, 1)
void k_gemm() {
    extern __shared__ char smem[];
    const int tid = threadIdx.x;
    const int w = tid >> 5, l = tid & 31;
    const int m0 = blockIdx.x * 128;
    const uint32_t sb = smem_u32(smem);

    const int wm = (w >> 2) * 32;     // 4 (m) x 4 (n) warp grid, 32x64 tiles
    const int wn = (w & 3) * 64;
    // ldmatrix lane->address maps
    const int ra  = (l & 7) + ((l >> 3) & 1) * 8;  // A row in 16x16
    const int kca = (l >> 4) * 8;                  // A k-col
    const int rb  = (l & 7) + (l >> 4) * 8;        // B row (n) in 16x16
    const int kcb = ((l >> 3) & 1) * 8;            // B k-col

    float acc[2][8][4];
#pragma unroll
    for (int a = 0; a < 2; a++)
#pragma unroll
        for (int b = 0; b < 8; b++)
#pragma unroll
            for (int c = 0; c < 4; c++) acc[a][b][c] = 0.f;

    load_stage(sb, 0, m0, tid); CP_COMMIT();
    load_stage(sb, 1, m0, tid); CP_COMMIT();

    for (int kt = 0; kt < 8; kt++) {
        CP_WAIT1();
        __syncthreads();
        if (kt + 2 < 8) { load_stage(sb, kt + 2, m0, tid); CP_COMMIT(); }

        const uint32_t ab = sb + (kt % 3) * STAGE;
#pragma unroll
        for (int k16 = 0; k16 < 32; k16 += 16) {
            uint32_t ah[2][4], al[2][4];
#pragma unroll
            for (int mi = 0; mi < 2; mi++) {
                uint32_t arow = ab + (wm + 16 * mi + ra) * 80 + (k16 + kca) * 2;
                LDSM4(ah[mi], arow + OFF_AH);
                LDSM4(al[mi], arow + OFF_AL);
            }
#pragma unroll
            for (int ng = 0; ng < 4; ng++) {
                uint32_t brow = ab + OFF_BH + (wn + 16 * ng + rb) * 80 + (k16 + kcb) * 2;
                uint32_t bh[4], bl[4];
                LDSM4(bh, brow);
                LDSM4(bl, brow + STG_B);
                // pass-major order: same-acc reuse distance = 4 MMAs
#pragma unroll
                for (int mi = 0; mi < 2; mi++) {
                    mma16816(acc[mi][2 * ng],     ah[mi], bh[0], bh[1]);
                    mma16816(acc[mi][2 * ng + 1], ah[mi], bh[2], bh[3]);
                }
#pragma unroll
                for (int mi = 0; mi < 2; mi++) {
                    mma16816(acc[mi][2 * ng],     al[mi], bh[0], bh[1]);
                    mma16816(acc[mi][2 * ng + 1], al[mi], bh[2], bh[3]);
                }
#pragma unroll
                for (int mi = 0; mi < 2; mi++) {
                    mma16816(acc[mi][2 * ng],     ah[mi], bl[0], bl[1]);
                    mma16816(acc[mi][2 * ng + 1], ah[mi], bl[2], bl[3]);
                }
            }
        }
    }

    // epilogue: acc -> g_msg
#pragma unroll
    for (int mi = 0; mi < 2; mi++) {
#pragma unroll
        for (int h = 0; h < 2; h++) {
            int row = m0 + wm + 16 * mi + (l >> 2) + 8 * h;
            if (row < N0c) {
                float* dst = &g_msg[(size_t)row * Dc + wn + 2 * (l & 3)];
#pragma unroll
                for (int nj = 0; nj < 8; nj++) {
                    float2 f = make_float2(acc[mi][nj][2 * h], acc[mi][nj][2 * h + 1]);
                    *(float2*)(dst + 8 * nj) = f;
                }
            }
        }
    }
}

// ---------------- pull aggregation + elu ------------------------------------
__global__ void k_agg(float* __restrict__ out) {
    int row = blockIdx.x * 4 + (threadIdx.x >> 6);
    int t = threadIdx.x & 63;
    if (row >= N1c) return;
    int s = g_start[row];
    int n = g_count[row];
    const float4* msg4 = (const float4*)g_msg;
    float4 acc = make_float4(0.f, 0.f, 0.f, 0.f);
    for (int j = 0; j < n; j++) {
        int c = g_ecol[s + j];
        float v = g_eval[s + j];
        float4 m = msg4[(size_t)c * 64 + t];
        acc.x += v * m.x;
        acc.y += v * m.y;
        acc.z += v * m.z;
        acc.w += v * m.w;
    }
    acc.x = acc.x > 0.f ? acc.x : expm1f(acc.x);
    acc.y = acc.y > 0.f ? acc.y : expm1f(acc.y);
    acc.z = acc.z > 0.f ? acc.z : expm1f(acc.z);
    acc.w = acc.w > 0.f ? acc.w : expm1f(acc.w);
    ((float4*)out)[(size_t)row * 64 + t] = acc;
}

// ---------------- launch ------------------------------------------------------
static cudaStream_t g_s1;
static cudaEvent_t  g_evFork, g_evJoin;

extern "C" void kernel_launch(void* const* d_in, const int* in_sizes, int n_in,
                              void* d_out, int out_size) {
    const float* x0   = (const float*)d_in[0];
    const int*   rows = (const int*)d_in[2];
    const int*   cols = (const int*)d_in[3];
    const float* vals = (const float*)d_in[4];
    const float* W    = (const float*)d_in[5];
    float* out = (float*)d_out;

    static bool once = []() {
        cudaFuncSetAttribute(k_gemm, cudaFuncAttributeMaxDynamicSharedMemorySize, GEMM_SMEM);
        cudaStreamCreateWithFlags(&g_s1, cudaStreamNonBlocking);
        cudaEventCreateWithFlags(&g_evFork, cudaEventDisableTiming);
        cudaEventCreateWithFlags(&g_evJoin, cudaEventDisableTiming);
        return true;
    }();
    (void)once;

    // fork: CSR build on side stream, prep+GEMM on main stream
    cudaEventRecord(g_evFork, 0);
    cudaStreamWaitEvent(g_s1, g_evFork, 0);

    k_zero_count<<<(N1c + 255) / 256, 256, 0, g_s1>>>();
    k_hist<<<(NNZc + 255) / 256, 256, 0, g_s1>>>(rows);
    k_scan_a<<<98, 256, 0, g_s1>>>();
    k_scan_b<<<1, 128, 0, g_s1>>>(98);
    k_scan_c<<<(N1c + 255) / 256, 256, 0, g_s1>>>();
    k_scatter<<<(NNZc + 255) / 256, 256, 0, g_s1>>>(rows, cols, vals);
    cudaEventRecord(g_evJoin, g_s1);

    k_wprep<<<Dc, 256>>>(W);
    k_xprep<<<25000, 256>>>(x0);
    k_gemm<<<(N0c + 127) / 128, 512, GEMM_SMEM>>>();

    // join, then aggregate
    cudaStreamWaitEvent(0, g_evJoin, 0);
    k_agg<<<(N1c + 3) / 4, 256>>>(out);
}